// round 8
// baseline (speedup 1.0000x reference)
#include <cuda_runtime.h>
#include <cstdint>
#include <cstddef>

#define HLD 132
#define HSZ (128 * HLD)
#define SMEM_BYTES ((3 * HSZ + 640 + 512) * 4)

// ---- static device scratch (no allocation allowed) ----
__device__ __align__(16) float g_Wsw[131072];  // swizzled tf32 [g][half][kt][lane][nt][2]
__device__ float g_gb[512];
__device__ float g_ca[128 * 128], g_cb[128 * 128], g_cc[128 * 128];
__device__ float g_mom[128 * 5];
__device__ float g_mu2[128 * 5], g_rs2[128 * 5];

// ---- helpers ----
__device__ __forceinline__ uint32_t tf32u(float f) {
  uint32_t u;
  asm("cvt.rna.tf32.f32 %0,%1;" : "=r"(u) : "f"(f));
  return u;
}
__device__ __forceinline__ float tanh_ap(float x) {
  float y;
  asm("tanh.approx.f32 %0,%1;" : "=f"(y) : "f"(x));
  return y;
}
__device__ __forceinline__ float sig_ap(float x) {
  return fmaf(tanh_ap(0.5f * x), 0.5f, 0.5f);
}
__device__ __forceinline__ void mma8(float (&d)[4], uint32_t a0, uint32_t a1,
                                     uint32_t a2, uint32_t a3, float b0, float b1) {
  asm volatile(
      "mma.sync.aligned.m16n8k8.row.col.f32.tf32.tf32.f32 "
      "{%0,%1,%2,%3},{%4,%5,%6,%7},{%8,%9},{%0,%1,%2,%3};\n"
      : "+f"(d[0]), "+f"(d[1]), "+f"(d[2]), "+f"(d[3])
      : "r"(a0), "r"(a1), "r"(a2), "r"(a3), "r"(__float_as_uint(b0)),
        "r"(__float_as_uint(b1)));
}

// 16 k-tiles of the chunk GEMM. A fp32 in SMEM (hi/lo split at load), B = swizzled
// tf32 weights (LDG.128). acc[8 ntiles][4].
__device__ __forceinline__ void k16(const float* __restrict__ A,
                                    const float4* __restrict__ w4, int r0, int kl,
                                    float (&acc)[8][4]) {
#pragma unroll 2
  for (int kt = 0; kt < 16; kt++) {
    const float* ap = A + kt * 8 + kl;
    float v0 = ap[r0 * HLD], v1 = ap[(r0 + 8) * HLD];
    float v2 = ap[r0 * HLD + 4], v3 = ap[(r0 + 8) * HLD + 4];
    uint32_t h0 = tf32u(v0), h1 = tf32u(v1), h2 = tf32u(v2), h3 = tf32u(v3);
    uint32_t l0 = tf32u(v0 - __uint_as_float(h0));
    uint32_t l1 = tf32u(v1 - __uint_as_float(h1));
    uint32_t l2 = tf32u(v2 - __uint_as_float(h2));
    uint32_t l3 = tf32u(v3 - __uint_as_float(h3));
    const float4* q = w4 + kt * 128;
    float4 q0 = q[0], q1 = q[1], q2 = q[2], q3 = q[3];
    mma8(acc[0], l0, l1, l2, l3, q0.x, q0.y);
    mma8(acc[1], l0, l1, l2, l3, q0.z, q0.w);
    mma8(acc[2], l0, l1, l2, l3, q1.x, q1.y);
    mma8(acc[3], l0, l1, l2, l3, q1.z, q1.w);
    mma8(acc[4], l0, l1, l2, l3, q2.x, q2.y);
    mma8(acc[5], l0, l1, l2, l3, q2.z, q2.w);
    mma8(acc[6], l0, l1, l2, l3, q3.x, q3.y);
    mma8(acc[7], l0, l1, l2, l3, q3.z, q3.w);
    mma8(acc[0], h0, h1, h2, h3, q0.x, q0.y);
    mma8(acc[1], h0, h1, h2, h3, q0.z, q0.w);
    mma8(acc[2], h0, h1, h2, h3, q1.x, q1.y);
    mma8(acc[3], h0, h1, h2, h3, q1.z, q1.w);
    mma8(acc[4], h0, h1, h2, h3, q2.x, q2.y);
    mma8(acc[5], h0, h1, h2, h3, q2.z, q2.w);
    mma8(acc[6], h0, h1, h2, h3, q3.x, q3.y);
    mma8(acc[7], h0, h1, h2, h3, q3.z, q3.w);
  }
}

template <int G, int HALF>
__device__ __forceinline__ void chunk_gemm(const float* __restrict__ E,
                                           const float* __restrict__ Hc, int r0,
                                           int lane, float (&acc)[8][4]) {
#pragma unroll
  for (int n = 0; n < 8; n++) {
    acc[n][0] = 0.f; acc[n][1] = 0.f; acc[n][2] = 0.f; acc[n][3] = 0.f;
  }
  const float4* wb =
      reinterpret_cast<const float4*>(g_Wsw) + ((G * 2 + HALF) * 1024 + lane) * 4;
  k16(E, wb, r0, lane & 3, acc);        // k 0..127  (e part)
  k16(Hc, wb + 2048, r0, lane & 3, acc);// k 128..255 (h part)
}

// One 64-cell half: I -> G -> F -> O. c in registers; writes h (SMEM) + z2 partials.
template <int HALF>
__device__ __forceinline__ void process_half(
    const float* __restrict__ E, const float* __restrict__ Hc, float* __restrict__ Hn,
    const float* __restrict__ ws, const float* __restrict__ gbs, int r0, int lane,
    float (&ch)[8][4], float (&zA)[5], float (&zB)[5]) {
  float acc[8][4], ig[8][4];
  const int cb0 = (HALF << 6) + 2 * (lane & 3);
  chunk_gemm<0, HALF>(E, Hc, r0, lane, acc);  // i-gate
#pragma unroll
  for (int nt = 0; nt < 8; nt++) {
    float2 gv = *reinterpret_cast<const float2*>(gbs + cb0 + nt * 8);
    ig[nt][0] = sig_ap(acc[nt][0] + gv.x);
    ig[nt][1] = sig_ap(acc[nt][1] + gv.y);
    ig[nt][2] = sig_ap(acc[nt][2] + gv.x);
    ig[nt][3] = sig_ap(acc[nt][3] + gv.y);
  }
  chunk_gemm<2, HALF>(E, Hc, r0, lane, acc);  // g-gate
#pragma unroll
  for (int nt = 0; nt < 8; nt++) {
    float2 gv = *reinterpret_cast<const float2*>(gbs + 256 + cb0 + nt * 8);
    ig[nt][0] *= tanh_ap(acc[nt][0] + gv.x);
    ig[nt][1] *= tanh_ap(acc[nt][1] + gv.y);
    ig[nt][2] *= tanh_ap(acc[nt][2] + gv.x);
    ig[nt][3] *= tanh_ap(acc[nt][3] + gv.y);
  }
  chunk_gemm<1, HALF>(E, Hc, r0, lane, acc);  // f-gate
#pragma unroll
  for (int nt = 0; nt < 8; nt++) {
    float2 gv = *reinterpret_cast<const float2*>(gbs + 128 + cb0 + nt * 8);
    ch[nt][0] = fmaf(sig_ap(acc[nt][0] + gv.x), ch[nt][0], ig[nt][0]);
    ch[nt][1] = fmaf(sig_ap(acc[nt][1] + gv.y), ch[nt][1], ig[nt][1]);
    ch[nt][2] = fmaf(sig_ap(acc[nt][2] + gv.x), ch[nt][2], ig[nt][2]);
    ch[nt][3] = fmaf(sig_ap(acc[nt][3] + gv.y), ch[nt][3], ig[nt][3]);
  }
  chunk_gemm<3, HALF>(E, Hc, r0, lane, acc);  // o-gate
#pragma unroll
  for (int nt = 0; nt < 8; nt++) {
    float2 gv = *reinterpret_cast<const float2*>(gbs + 384 + cb0 + nt * 8);
    float h00 = sig_ap(acc[nt][0] + gv.x) * tanh_ap(ch[nt][0]);
    float h01 = sig_ap(acc[nt][1] + gv.y) * tanh_ap(ch[nt][1]);
    float h10 = sig_ap(acc[nt][2] + gv.x) * tanh_ap(ch[nt][2]);
    float h11 = sig_ap(acc[nt][3] + gv.y) * tanh_ap(ch[nt][3]);
    int c0 = cb0 + nt * 8;
    *reinterpret_cast<float2*>(Hn + r0 * HLD + c0) = make_float2(h00, h01);
    *reinterpret_cast<float2*>(Hn + (r0 + 8) * HLD + c0) = make_float2(h10, h11);
#pragma unroll
    for (int o = 0; o < 5; o++) {
      float2 wv = *reinterpret_cast<const float2*>(ws + o * 128 + c0);
      zA[o] = fmaf(h00, wv.x, fmaf(h01, wv.y, zA[o]));
      zB[o] = fmaf(h10, wv.x, fmaf(h11, wv.y, zB[o]));
    }
  }
}

// ---- main recurrent kernel: 256 CTAs x 256 thr, 128 rows/CTA, all 128 steps ----
__global__ void __launch_bounds__(256, 1)
    k_main(const float* __restrict__ x, const float* __restrict__ wout,
           float* __restrict__ out) {
  extern __shared__ float sm_[];
  float* E = sm_;                 // [128][132] embeddings (per step)
  float* Hb = sm_ + HSZ;          // [2][128][132] h double buffer
  float* ws = sm_ + 3 * HSZ;      // [5][128] w_out
  float* gbs = ws + 640;          // [512] gate bias
  const int tid = threadIdx.x, lane = tid & 31, wid = tid >> 5;
  const int bg0 = blockIdx.x << 7;
  const int r0 = (wid << 4) + (lane >> 2);
  for (int i = tid; i < 640; i += 256) ws[i] = wout[i];
  for (int i = tid; i < 512; i += 256) gbs[i] = g_gb[i];
  for (int i = tid; i < HSZ; i += 256) Hb[i] = 0.f;
  float c0r[8][4], c1r[8][4];
#pragma unroll
  for (int n = 0; n < 8; n++)
#pragma unroll
    for (int e = 0; e < 4; e++) { c0r[n][e] = 0.f; c1r[n][e] = 0.f; }
  __syncthreads();
  const int er = tid >> 1, jb = (tid & 1) << 6;
  for (int t = 0; t < 128; t++) {
    // e = relu(ca*x0 + cb*x1 + cc)  (BN1 folded into affine coefficients)
    float2 xv = *reinterpret_cast<const float2*>(
        x + (((size_t)(bg0 + er)) * 128 + t) * 2);
    const float4* ca4 = reinterpret_cast<const float4*>(g_ca + t * 128 + jb);
    const float4* cb4 = reinterpret_cast<const float4*>(g_cb + t * 128 + jb);
    const float4* cc4 = reinterpret_cast<const float4*>(g_cc + t * 128 + jb);
    float* Er = E + er * HLD + jb;
#pragma unroll
    for (int q = 0; q < 16; q++) {
      float4 A4 = ca4[q], B4 = cb4[q], C4 = cc4[q], ev;
      ev.x = fmaxf(fmaf(A4.x, xv.x, fmaf(B4.x, xv.y, C4.x)), 0.f);
      ev.y = fmaxf(fmaf(A4.y, xv.x, fmaf(B4.y, xv.y, C4.y)), 0.f);
      ev.z = fmaxf(fmaf(A4.z, xv.x, fmaf(B4.z, xv.y, C4.z)), 0.f);
      ev.w = fmaxf(fmaf(A4.w, xv.x, fmaf(B4.w, xv.y, C4.w)), 0.f);
      reinterpret_cast<float4*>(Er)[q] = ev;
    }
    __syncthreads();
    const float* Hc = Hb + (t & 1) * HSZ;
    float* Hn = Hb + ((t + 1) & 1) * HSZ;
    float zA[5] = {0.f, 0.f, 0.f, 0.f, 0.f}, zB[5] = {0.f, 0.f, 0.f, 0.f, 0.f};
    process_half<0>(E, Hc, Hn, ws, gbs, r0, lane, c0r, zA, zB);
    process_half<1>(E, Hc, Hn, ws, gbs, r0, lane, c1r, zA, zB);
#pragma unroll
    for (int o = 0; o < 5; o++) {
      zA[o] += __shfl_xor_sync(0xffffffffu, zA[o], 1);
      zA[o] += __shfl_xor_sync(0xffffffffu, zA[o], 2);
      zB[o] += __shfl_xor_sync(0xffffffffu, zB[o], 1);
      zB[o] += __shfl_xor_sync(0xffffffffu, zB[o], 2);
    }
    if ((lane & 3) == 0) {
      size_t oA = (((size_t)(bg0 + r0)) * 128 + t) * 5;
      size_t oB = (((size_t)(bg0 + r0 + 8)) * 128 + t) * 5;
#pragma unroll
      for (int o = 0; o < 5; o++) { out[oA + o] = zA[o]; out[oB + o] = zB[o]; }
    }
    __syncthreads();
  }
}

// ---- prep: batch moments of x per t ----
__global__ void k_moms(const float* __restrict__ x) {
  const int t = blockIdx.x, tid = threadIdx.x, lane = tid & 31, wid = tid >> 5;
  float s[5] = {0.f, 0.f, 0.f, 0.f, 0.f};
  for (int b = tid; b < 32768; b += 256) {
    float2 v = *reinterpret_cast<const float2*>(x + ((size_t)b * 128 + t) * 2);
    s[0] += v.x; s[1] += v.y; s[2] += v.x * v.x; s[3] += v.x * v.y; s[4] += v.y * v.y;
  }
  __shared__ float sh[5][8];
#pragma unroll
  for (int i = 0; i < 5; i++)
    for (int off = 16; off; off >>= 1) s[i] += __shfl_down_sync(0xffffffffu, s[i], off);
  if (lane == 0)
#pragma unroll
    for (int i = 0; i < 5; i++) sh[i][wid] = s[i];
  __syncthreads();
  if (tid == 0) {
#pragma unroll
    for (int i = 0; i < 5; i++) {
      float v = 0.f;
      for (int w = 0; w < 8; w++) v += sh[i][w];
      g_mom[t * 5 + i] = v;
    }
  }
}

// ---- prep: fold BN1 into per-(t,j) affine coefficients ----
__global__ void k_coef(const float* __restrict__ w_emb, const float* __restrict__ b_emb,
                       const float* __restrict__ gamma1,
                       const float* __restrict__ beta1) {
  const int t = blockIdx.x, j = threadIdx.x;
  const float invB = 1.f / 32768.f;
  float m0 = g_mom[t * 5 + 0] * invB, m1 = g_mom[t * 5 + 1] * invB;
  float c00 = g_mom[t * 5 + 2] * invB - m0 * m0;
  float c01 = g_mom[t * 5 + 3] * invB - m0 * m1;
  float c11 = g_mom[t * 5 + 4] * invB - m1 * m1;
  float w0 = w_emb[j * 2], w1 = w_emb[j * 2 + 1], bb = b_emb[j];
  float um = w0 * m0 + w1 * m1 + bb;
  float uv = w0 * w0 * c00 + 2.f * w0 * w1 * c01 + w1 * w1 * c11;
  float r = gamma1[j] * rsqrtf(uv + 1e-5f);
  g_ca[t * 128 + j] = r * w0;
  g_cb[t * 128 + j] = r * w1;
  g_cc[t * 128 + j] = r * (bb - um) + beta1[j];
}

// ---- prep: tf32-round + swizzle combined weights into fragment order ----
__global__ void k_wsw(const float* __restrict__ w_ih, const float* __restrict__ w_hh,
                      const float* __restrict__ b_ih, const float* __restrict__ b_hh) {
  const int idx = blockIdx.x * 256 + threadIdx.x;  // 131072 entries
  if (idx < 512) g_gb[idx] = b_ih[idx] + b_hh[idx];
  int e = idx & 1, nt = (idx >> 1) & 7, lane = (idx >> 4) & 31;
  int kt = (idx >> 9) & 31, gh = idx >> 14;
  int g = gh >> 1, half = gh & 1;
  int k = kt * 8 + (lane & 3) + (e ? 4 : 0);
  int n = g * 128 + half * 64 + nt * 8 + (lane >> 2);
  float v = (k < 128) ? w_ih[n * 128 + k] : w_hh[n * 128 + (k - 128)];
  g_Wsw[idx] = __uint_as_float(tf32u(v));
}

// ---- deferred BN2: stats over batch per (t, o) ----
__global__ void k_bnstats(const float* __restrict__ out) {
  const int t = blockIdx.x, tid = threadIdx.x, lane = tid & 31, wid = tid >> 5;
  float s[5] = {0.f, 0.f, 0.f, 0.f, 0.f}, q[5] = {0.f, 0.f, 0.f, 0.f, 0.f};
  for (int b = tid; b < 32768; b += 256) {
    const float* p = out + ((size_t)b * 128 + t) * 5;
#pragma unroll
    for (int o = 0; o < 5; o++) { float v = p[o]; s[o] += v; q[o] += v * v; }
  }
  __shared__ float sh[10][8];
#pragma unroll
  for (int o = 0; o < 5; o++)
    for (int off = 16; off; off >>= 1) {
      s[o] += __shfl_down_sync(0xffffffffu, s[o], off);
      q[o] += __shfl_down_sync(0xffffffffu, q[o], off);
    }
  if (lane == 0)
#pragma unroll
    for (int o = 0; o < 5; o++) { sh[o][wid] = s[o]; sh[5 + o][wid] = q[o]; }
  __syncthreads();
  if (tid == 0) {
#pragma unroll
    for (int o = 0; o < 5; o++) {
      float S = 0.f, Q = 0.f;
      for (int w = 0; w < 8; w++) { S += sh[o][w]; Q += sh[5 + o][w]; }
      float mu = S / 32768.f, var = Q / 32768.f - mu * mu;
      g_mu2[t * 5 + o] = mu;
      g_rs2[t * 5 + o] = rsqrtf(var + 1e-5f);
    }
  }
}

// ---- deferred BN2: normalize + relu in place ----
__global__ void k_bnnorm(float* __restrict__ out, const float* __restrict__ gamma2,
                         const float* __restrict__ beta2) {
  size_t i = (size_t)blockIdx.x * 256 + threadIdx.x;
  if (i >= (size_t)32768 * 128 * 5) return;
  int o = (int)(i % 5);
  int t = (int)((i / 5) & 127);
  float mu = g_mu2[t * 5 + o], rs = g_rs2[t * 5 + o];
  float v = out[i];
  out[i] = fmaxf(fmaf(gamma2[o] * rs, v - mu, beta2[o]), 0.f);
}

extern "C" void kernel_launch(void* const* d_in, const int* in_sizes, int n_in,
                              void* d_out, int out_size) {
  const float* x = (const float*)d_in[0];
  const float* w_emb = (const float*)d_in[1];
  const float* b_emb = (const float*)d_in[2];
  const float* gamma1 = (const float*)d_in[3];
  const float* beta1 = (const float*)d_in[4];
  const float* w_ih = (const float*)d_in[5];
  const float* w_hh = (const float*)d_in[6];
  const float* b_ih = (const float*)d_in[7];
  const float* b_hh = (const float*)d_in[8];
  const float* w_out = (const float*)d_in[9];
  const float* gamma2 = (const float*)d_in[11];
  const float* beta2 = (const float*)d_in[12];
  float* out = (float*)d_out;
  cudaFuncSetAttribute(k_main, cudaFuncAttributeMaxDynamicSharedMemorySize, SMEM_BYTES);
  k_moms<<<128, 256>>>(x);
  k_coef<<<128, 128>>>(w_emb, b_emb, gamma1, beta1);
  k_wsw<<<512, 256>>>(w_ih, w_hh, b_ih, b_hh);
  k_main<<<256, 256, SMEM_BYTES>>>(x, w_out, out);
  k_bnstats<<<128, 256>>>(out);
  k_bnnorm<<<81920, 256>>>(out, gamma2, beta2);
}

// round 9
// speedup vs baseline: 2.4629x; 2.4629x over previous
#include <cuda_runtime.h>
#include <cstdint>
#include <cstddef>

#define HLD 132
// smem floats: Wb 16384 | E 16896 | H 16896 | ws 640 | gbs 512 | zb 640
#define SMEM_FLOATS (16384 + 16896 + 16896 + 640 + 512 + 640)
#define SMEM_BYTES (SMEM_FLOATS * 4)

__device__ __align__(16) float g_W2[131072];  // [slab32][kt4][nt16][lane32][e2] tf32
__device__ float g_gb[512];
__device__ float g_ca[16384], g_cb[16384], g_cc[16384];
__device__ float g_mom[640];
__device__ float g_mu2[640], g_rs2[640];

__device__ __forceinline__ uint32_t tf32u(float f) {
  uint32_t u;
  asm("cvt.rna.tf32.f32 %0,%1;" : "=r"(u) : "f"(f));
  return u;
}
__device__ __forceinline__ float tf32f(float f) { return __uint_as_float(tf32u(f)); }
__device__ __forceinline__ float tanh_ap(float x) {
  float y;
  asm("tanh.approx.f32 %0,%1;" : "=f"(y) : "f"(x));
  return y;
}
__device__ __forceinline__ float sig_ap(float x) {
  return fmaf(tanh_ap(0.5f * x), 0.5f, 0.5f);
}
__device__ __forceinline__ void mma8(float (&d)[4], float a0, float a1, float a2,
                                     float a3, float b0, float b1) {
  asm volatile(
      "mma.sync.aligned.m16n8k8.row.col.f32.tf32.tf32.f32 "
      "{%0,%1,%2,%3},{%4,%5,%6,%7},{%8,%9},{%0,%1,%2,%3};\n"
      : "+f"(d[0]), "+f"(d[1]), "+f"(d[2]), "+f"(d[3])
      : "r"(__float_as_uint(a0)), "r"(__float_as_uint(a1)),
        "r"(__float_as_uint(a2)), "r"(__float_as_uint(a3)),
        "r"(__float_as_uint(b0)), "r"(__float_as_uint(b1)));
}
__device__ __forceinline__ void issue_slab(float* Wb, int s, int tid) {
  uint32_t sa = (uint32_t)__cvta_generic_to_shared(Wb + (s & 3) * 4096 + tid * 16);
  const char* gp = (const char*)(g_W2 + (size_t)s * 4096 + tid * 16);
  asm volatile("cp.async.cg.shared.global [%0], [%1], 16;" ::"r"(sa), "l"(gp));
  asm volatile("cp.async.cg.shared.global [%0], [%1], 16;" ::"r"(sa + 16), "l"(gp + 16));
  asm volatile("cp.async.cg.shared.global [%0], [%1], 16;" ::"r"(sa + 32), "l"(gp + 32));
  asm volatile("cp.async.cg.shared.global [%0], [%1], 16;" ::"r"(sa + 48), "l"(gp + 48));
  asm volatile("cp.async.commit_group;" ::: "memory");
}

// ---- main recurrent kernel: 256 CTAs x 256 thr, 128 rows/CTA, 128 steps ----
__global__ void __launch_bounds__(256, 1)
    k_main(const float* __restrict__ x, const float* __restrict__ wout,
           float* __restrict__ out) {
  extern __shared__ float sm[];
  float* Wb = sm;
  float* E = sm + 16384;
  float* H = E + 16896;
  float* ws = H + 16896;
  float* gbs = ws + 640;
  float* zb = gbs + 512;
  const int tid = threadIdx.x, lane = tid & 31, wid = tid >> 5;
  const int rg = wid >> 1, cg = wid & 1, lg = lane >> 2, q = lane & 3;
  const int bg0 = blockIdx.x << 7;
  for (int i = tid; i < 640; i += 256) ws[i] = wout[i];
  for (int i = tid; i < 512; i += 256) gbs[i] = g_gb[i];
  for (int i = tid; i < 16896; i += 256) H[i] = 0.f;
  float c[2][8][4], acc[2][8][4], ig[2][8][4];
#pragma unroll
  for (int m = 0; m < 2; m++)
#pragma unroll
    for (int nt = 0; nt < 8; nt++)
#pragma unroll
      for (int e = 0; e < 4; e++) c[m][nt][e] = 0.f;
  __syncthreads();
  const int er = tid >> 1, jb = (tid & 1) << 4;
  const size_t xo = (size_t)(bg0 + er) * 256;
  const int ar = (32 * rg + lg) * HLD;
  const int bofs[4] = {0, 256, 128, 384};  // stream i,g,f,o -> pytorch offsets

  for (int t = 0; t < 128; t++) {
    issue_slab(Wb, 0, tid);
    // ---- E fill: e = relu(ca*x0+cb*x1+cc), tf32-rounded (BN1 folded) ----
    {
      float2 xv = *reinterpret_cast<const float2*>(x + xo + 2 * t);
      const float4* A4 = reinterpret_cast<const float4*>(g_ca + t * 128) + jb;
      const float4* B4 = reinterpret_cast<const float4*>(g_cb + t * 128) + jb;
      const float4* C4 = reinterpret_cast<const float4*>(g_cc + t * 128) + jb;
      float* Er = E + er * HLD + ((tid & 1) << 6);
#pragma unroll
      for (int i = 0; i < 16; i++) {
        float4 a = A4[i], b = B4[i], cc4 = C4[i], ev;
        ev.x = tf32f(fmaxf(fmaf(a.x, xv.x, fmaf(b.x, xv.y, cc4.x)), 0.f));
        ev.y = tf32f(fmaxf(fmaf(a.y, xv.x, fmaf(b.y, xv.y, cc4.y)), 0.f));
        ev.z = tf32f(fmaxf(fmaf(a.z, xv.x, fmaf(b.z, xv.y, cc4.z)), 0.f));
        ev.w = tf32f(fmaxf(fmaf(a.w, xv.x, fmaf(b.w, xv.y, cc4.w)), 0.f));
        *reinterpret_cast<float4*>(Er + 4 * i) = ev;
      }
    }
    for (int s = 0; s < 32; s++) {
      if ((s & 7) == 0) {
#pragma unroll
        for (int m = 0; m < 2; m++)
#pragma unroll
          for (int nt = 0; nt < 8; nt++)
#pragma unroll
            for (int e = 0; e < 4; e++) acc[m][nt][e] = 0.f;
      }
      if (s < 31) {
        issue_slab(Wb, s + 1, tid);
        asm volatile("cp.async.wait_group 1;" ::: "memory");
      } else {
        asm volatile("cp.async.wait_group 0;" ::: "memory");
      }
      __syncthreads();
      // ---- consume slab s: 4 k-tiles, warp tile 32 rows x 64 cols ----
      const float* Ab = ((s >> 2) & 1) ? H : E;
      const float* Bb = Wb + (s & 3) * 4096;
      const int kb = (s & 3) * 32;
#pragma unroll
      for (int kt = 0; kt < 4; kt++) {
        const float* ap = Ab + ar + kb + kt * 8 + q;
        float a00 = ap[0], a01 = ap[8 * HLD], a02 = ap[4], a03 = ap[8 * HLD + 4];
        float a10 = ap[16 * HLD], a11 = ap[24 * HLD];
        float a12 = ap[16 * HLD + 4], a13 = ap[24 * HLD + 4];
        const float2* bp =
            reinterpret_cast<const float2*>(Bb) + (kt * 16 + cg * 8) * 32 + lane;
#pragma unroll
        for (int nt = 0; nt < 8; nt++) {
          float2 bv = bp[nt * 32];
          mma8(acc[0][nt], a00, a01, a02, a03, bv.x, bv.y);
          mma8(acc[1][nt], a10, a11, a12, a13, bv.x, bv.y);
        }
      }
      if ((s & 7) != 7) continue;
      const int sg = s >> 3;
      const float* gb = gbs + bofs[sg] + cg * 64 + 2 * q;
      if (sg == 0) {  // i-gate
#pragma unroll
        for (int m = 0; m < 2; m++)
#pragma unroll
          for (int nt = 0; nt < 8; nt++) {
            float2 gv = *reinterpret_cast<const float2*>(gb + 8 * nt);
            ig[m][nt][0] = sig_ap(acc[m][nt][0] + gv.x);
            ig[m][nt][1] = sig_ap(acc[m][nt][1] + gv.y);
            ig[m][nt][2] = sig_ap(acc[m][nt][2] + gv.x);
            ig[m][nt][3] = sig_ap(acc[m][nt][3] + gv.y);
          }
      } else if (sg == 1) {  // g-gate
#pragma unroll
        for (int m = 0; m < 2; m++)
#pragma unroll
          for (int nt = 0; nt < 8; nt++) {
            float2 gv = *reinterpret_cast<const float2*>(gb + 8 * nt);
            ig[m][nt][0] *= tanh_ap(acc[m][nt][0] + gv.x);
            ig[m][nt][1] *= tanh_ap(acc[m][nt][1] + gv.y);
            ig[m][nt][2] *= tanh_ap(acc[m][nt][2] + gv.x);
            ig[m][nt][3] *= tanh_ap(acc[m][nt][3] + gv.y);
          }
      } else if (sg == 2) {  // f-gate
#pragma unroll
        for (int m = 0; m < 2; m++)
#pragma unroll
          for (int nt = 0; nt < 8; nt++) {
            float2 gv = *reinterpret_cast<const float2*>(gb + 8 * nt);
            c[m][nt][0] = fmaf(sig_ap(acc[m][nt][0] + gv.x), c[m][nt][0], ig[m][nt][0]);
            c[m][nt][1] = fmaf(sig_ap(acc[m][nt][1] + gv.y), c[m][nt][1], ig[m][nt][1]);
            c[m][nt][2] = fmaf(sig_ap(acc[m][nt][2] + gv.x), c[m][nt][2], ig[m][nt][2]);
            c[m][nt][3] = fmaf(sig_ap(acc[m][nt][3] + gv.y), c[m][nt][3], ig[m][nt][3]);
          }
      } else {  // o-gate: h, H store, z2 partials
        __syncthreads();  // all H reads of this step complete before rewrite
        float zr[4][5];
#pragma unroll
        for (int sl = 0; sl < 4; sl++)
#pragma unroll
          for (int o = 0; o < 5; o++) zr[sl][o] = 0.f;
#pragma unroll
        for (int m = 0; m < 2; m++)
#pragma unroll
          for (int nt = 0; nt < 8; nt++) {
            float2 gv = *reinterpret_cast<const float2*>(gb + 8 * nt);
            float h0 = sig_ap(acc[m][nt][0] + gv.x) * tanh_ap(c[m][nt][0]);
            float h1 = sig_ap(acc[m][nt][1] + gv.y) * tanh_ap(c[m][nt][1]);
            float h2 = sig_ap(acc[m][nt][2] + gv.x) * tanh_ap(c[m][nt][2]);
            float h3 = sig_ap(acc[m][nt][3] + gv.y) * tanh_ap(c[m][nt][3]);
            const int col = cg * 64 + nt * 8 + 2 * q;
            const int ro = ar + 16 * m * HLD + col;
            *reinterpret_cast<float2*>(H + ro) = make_float2(tf32f(h0), tf32f(h1));
            *reinterpret_cast<float2*>(H + ro + 8 * HLD) =
                make_float2(tf32f(h2), tf32f(h3));
#pragma unroll
            for (int o = 0; o < 5; o++) {
              float2 wv = *reinterpret_cast<const float2*>(ws + o * 128 + col);
              zr[2 * m][o] = fmaf(h0, wv.x, fmaf(h1, wv.y, zr[2 * m][o]));
              zr[2 * m + 1][o] = fmaf(h2, wv.x, fmaf(h3, wv.y, zr[2 * m + 1][o]));
            }
          }
#pragma unroll
        for (int sl = 0; sl < 4; sl++)
#pragma unroll
          for (int o = 0; o < 5; o++) {
            zr[sl][o] += __shfl_xor_sync(0xffffffffu, zr[sl][o], 1);
            zr[sl][o] += __shfl_xor_sync(0xffffffffu, zr[sl][o], 2);
          }
        if (cg == 0 && q == 0) {
#pragma unroll
          for (int sl = 0; sl < 4; sl++)
#pragma unroll
            for (int o = 0; o < 5; o++)
              zb[(32 * rg + lg + 8 * sl) * 5 + o] = zr[sl][o];
        }
        __syncthreads();
        if (cg == 1 && q == 0) {
#pragma unroll
          for (int sl = 0; sl < 4; sl++) {
            int row = 32 * rg + lg + 8 * sl;
            size_t ob = ((size_t)(bg0 + row) * 128 + t) * 5;
#pragma unroll
            for (int o = 0; o < 5; o++) out[ob + o] = zr[sl][o] + zb[row * 5 + o];
          }
        }
      }
    }
  }
}

// ---- prep: batch moments of x per t ----
__global__ void k_moms(const float* __restrict__ x) {
  const int t = blockIdx.x, tid = threadIdx.x, lane = tid & 31, wid = tid >> 5;
  float s[5] = {0.f, 0.f, 0.f, 0.f, 0.f};
  for (int b = tid; b < 32768; b += 256) {
    float2 v = *reinterpret_cast<const float2*>(x + ((size_t)b * 128 + t) * 2);
    s[0] += v.x; s[1] += v.y; s[2] += v.x * v.x; s[3] += v.x * v.y; s[4] += v.y * v.y;
  }
  __shared__ float sh[5][8];
#pragma unroll
  for (int i = 0; i < 5; i++)
    for (int off = 16; off; off >>= 1) s[i] += __shfl_down_sync(0xffffffffu, s[i], off);
  if (lane == 0)
#pragma unroll
    for (int i = 0; i < 5; i++) sh[i][wid] = s[i];
  __syncthreads();
  if (tid == 0) {
#pragma unroll
    for (int i = 0; i < 5; i++) {
      float v = 0.f;
      for (int w = 0; w < 8; w++) v += sh[i][w];
      g_mom[t * 5 + i] = v;
    }
  }
}

// ---- prep: fold BN1 into per-(t,j) affine coefficients ----
__global__ void k_coef(const float* __restrict__ w_emb, const float* __restrict__ b_emb,
                       const float* __restrict__ gamma1,
                       const float* __restrict__ beta1) {
  const int t = blockIdx.x, j = threadIdx.x;
  const float invB = 1.f / 32768.f;
  float m0 = g_mom[t * 5 + 0] * invB, m1 = g_mom[t * 5 + 1] * invB;
  float c00 = g_mom[t * 5 + 2] * invB - m0 * m0;
  float c01 = g_mom[t * 5 + 3] * invB - m0 * m1;
  float c11 = g_mom[t * 5 + 4] * invB - m1 * m1;
  float w0 = w_emb[j * 2], w1 = w_emb[j * 2 + 1], bb = b_emb[j];
  float um = w0 * m0 + w1 * m1 + bb;
  float uv = w0 * w0 * c00 + 2.f * w0 * w1 * c01 + w1 * w1 * c11;
  float r = gamma1[j] * rsqrtf(uv + 1e-5f);
  g_ca[t * 128 + j] = r * w0;
  g_cb[t * 128 + j] = r * w1;
  g_cc[t * 128 + j] = r * (bb - um) + beta1[j];
}

// ---- prep: tf32-round + pack weights into slab/fragment order ----
__global__ void k_wsw(const float* __restrict__ w_ih, const float* __restrict__ w_hh,
                      const float* __restrict__ b_ih, const float* __restrict__ b_hh) {
  const int idx = blockIdx.x * 256 + threadIdx.x;  // 131072
  if (idx < 512) g_gb[idx] = b_ih[idx] + b_hh[idx];
  const int e = idx & 1, lane = (idx >> 1) & 31, nt = (idx >> 6) & 15;
  const int kt = (idx >> 10) & 3, s = idx >> 12;  // slab 0..31
  const int gmap[4] = {0, 2, 1, 3};               // stream i,g,f,o
  const int pg = gmap[s >> 3], part = (s >> 2) & 1;
  const int kl = (s & 3) * 32 + kt * 8 + (lane & 3) + 4 * e;
  const int n = pg * 128 + nt * 8 + (lane >> 2);
  const float* W = part ? w_hh : w_ih;
  g_W2[idx] = __uint_as_float(tf32u(W[n * 128 + kl]));
}

// ---- deferred BN2: stats over batch per (t, o) ----
__global__ void k_bnstats(const float* __restrict__ out) {
  const int t = blockIdx.x, tid = threadIdx.x, lane = tid & 31, wid = tid >> 5;
  float s[5] = {0.f, 0.f, 0.f, 0.f, 0.f}, qq[5] = {0.f, 0.f, 0.f, 0.f, 0.f};
  for (int b = tid; b < 32768; b += 256) {
    const float* p = out + ((size_t)b * 128 + t) * 5;
#pragma unroll
    for (int o = 0; o < 5; o++) { float v = p[o]; s[o] += v; qq[o] += v * v; }
  }
  __shared__ float sh[10][8];
#pragma unroll
  for (int o = 0; o < 5; o++)
    for (int off = 16; off; off >>= 1) {
      s[o] += __shfl_down_sync(0xffffffffu, s[o], off);
      qq[o] += __shfl_down_sync(0xffffffffu, qq[o], off);
    }
  if (lane == 0)
#pragma unroll
    for (int o = 0; o < 5; o++) { sh[o][wid] = s[o]; sh[5 + o][wid] = qq[o]; }
  __syncthreads();
  if (tid == 0) {
#pragma unroll
    for (int o = 0; o < 5; o++) {
      float S = 0.f, Q = 0.f;
      for (int w = 0; w < 8; w++) { S += sh[o][w]; Q += sh[5 + o][w]; }
      float mu = S / 32768.f, var = Q / 32768.f - mu * mu;
      g_mu2[t * 5 + o] = mu;
      g_rs2[t * 5 + o] = rsqrtf(var + 1e-5f);
    }
  }
}

// ---- deferred BN2: normalize + relu in place ----
__global__ void k_bnnorm(float* __restrict__ out, const float* __restrict__ gamma2,
                         const float* __restrict__ beta2) {
  size_t i = (size_t)blockIdx.x * 256 + threadIdx.x;
  if (i >= (size_t)32768 * 128 * 5) return;
  int o = (int)(i % 5);
  int t = (int)((i / 5) & 127);
  float v = out[i];
  out[i] = fmaxf(fmaf(gamma2[o] * g_rs2[t * 5 + o], v - g_mu2[t * 5 + o], beta2[o]), 0.f);
}

extern "C" void kernel_launch(void* const* d_in, const int* in_sizes, int n_in,
                              void* d_out, int out_size) {
  const float* x = (const float*)d_in[0];
  const float* w_emb = (const float*)d_in[1];
  const float* b_emb = (const float*)d_in[2];
  const float* gamma1 = (const float*)d_in[3];
  const float* beta1 = (const float*)d_in[4];
  const float* w_ih = (const float*)d_in[5];
  const float* w_hh = (const float*)d_in[6];
  const float* b_ih = (const float*)d_in[7];
  const float* b_hh = (const float*)d_in[8];
  const float* w_out = (const float*)d_in[9];
  const float* gamma2 = (const float*)d_in[11];
  const float* beta2 = (const float*)d_in[12];
  float* out = (float*)d_out;
  cudaFuncSetAttribute(k_main, cudaFuncAttributeMaxDynamicSharedMemorySize, SMEM_BYTES);
  k_moms<<<128, 256>>>(x);
  k_coef<<<128, 128>>>(w_emb, b_emb, gamma1, beta1);
  k_wsw<<<512, 256>>>(w_ih, w_hh, b_ih, b_hh);
  k_main<<<256, 256, SMEM_BYTES>>>(x, w_out, out);
  k_bnstats<<<128, 256>>>(out);
  k_bnnorm<<<81920, 256>>>(out, gamma2, beta2);
}